// round 2
// baseline (speedup 1.0000x reference)
#include <cuda_runtime.h>

#define GX 1024
#define GY 1024
#define GZ 40
#define NCELLS (GX * GY * GZ)
#define MAXV 60000
#define MAXP 32
#define BLK 256
#define NMAX 1250000
#define NBMAX ((NMAX + BLK - 1) / BLK)

// Scratch state. All zero-initialized by CUDA; every kernel invocation leaves
// the state back at all-zeros (self-cleaning) so graph replays are identical.
__device__ int      g_map[NCELLS];          // 0 = empty; >0 = (n-i) of first point; <0 = -(vid+1)
__device__ int      g_flat[NMAX];           // flat cell id per point, -1 invalid (fully overwritten)
__device__ unsigned g_repBits[(NMAX + 31) / 32 + 64];
__device__ int      g_blockCnt[NBMAX];
__device__ int      g_blockOff[NBMAX];
__device__ int      g_voxelNum;
__device__ unsigned g_slots[MAXV * MAXP];   // 0 = empty, else key = n - point_idx
__device__ int      g_cnt[MAXV];
__device__ int      g_coors[MAXV * 3];      // (z,y,x) staging; only [0,voxel_num) ever read

// ---------------------------------------------------------------------------
// K1: compute voxel coords, record flat id, atomicMax claim of first point.
// key = n - i  (larger key == earlier point; 0 stays "empty").
// ---------------------------------------------------------------------------
__global__ void k1_claim(const float4* __restrict__ pts, int n) {
    int i = blockIdx.x * BLK + threadIdx.x;
    if (i >= n) return;
    float4 p = pts[i];
    // Exactly mirror reference f32 math: floor((p - rmin) / vs)
    float fx = floorf((p.x - (-51.2f)) / 0.1f);
    float fy = floorf((p.y - (-51.2f)) / 0.1f);
    float fz = floorf((p.z - (-5.0f)) / 0.2f);
    int cx = (int)fx, cy = (int)fy, cz = (int)fz;
    int flat = -1;
    if (cx >= 0 && cx < GX && cy >= 0 && cy < GY && cz >= 0 && cz < GZ) {
        flat = (cx * GY + cy) * GZ + cz;
        atomicMax(&g_map[flat], n - i);
    }
    g_flat[i] = flat;
}

// ---------------------------------------------------------------------------
// K2: rep flags (point is the first point of its voxel) -> bitmask + block counts
// ---------------------------------------------------------------------------
__global__ void k2_flags(int n) {
    int i = blockIdx.x * BLK + threadIdx.x;
    int lane = threadIdx.x & 31;
    int rep = 0;
    if (i < n) {
        int f = g_flat[i];
        if (f >= 0 && g_map[f] == n - i) rep = 1;
    }
    unsigned m = __ballot_sync(0xffffffffu, rep);
    if (lane == 0) g_repBits[i >> 5] = m;
    __shared__ int ws[BLK / 32];
    if (lane == 0) ws[threadIdx.x >> 5] = __popc(m);
    __syncthreads();
    if (threadIdx.x == 0) {
        int s = 0;
        #pragma unroll
        for (int w = 0; w < BLK / 32; w++) s += ws[w];
        g_blockCnt[blockIdx.x] = s;
    }
}

// ---------------------------------------------------------------------------
// Single-block exclusive scan over per-block rep counts.
// ---------------------------------------------------------------------------
__global__ void k_scan(int nb) {
    __shared__ int sh[1024];
    int t = threadIdx.x;
    int per = (nb + 1023) >> 10;
    int base = t * per;
    int s = 0;
    for (int j = 0; j < per; j++) {
        int k = base + j;
        if (k < nb) s += g_blockCnt[k];
    }
    sh[t] = s;
    __syncthreads();
    int mysum = s;
    for (int off = 1; off < 1024; off <<= 1) {
        int v = (t >= off) ? sh[t - off] : 0;
        __syncthreads();
        sh[t] += v;
        __syncthreads();
    }
    int run = sh[t] - mysum;  // exclusive prefix for this thread's chunk
    for (int j = 0; j < per; j++) {
        int k = base + j;
        if (k < nb) {
            g_blockOff[k] = run;
            run += g_blockCnt[k];
        }
    }
    if (t == 1023) {
        int tot = sh[1023];
        g_voxelNum = tot < MAXV ? tot : MAXV;
    }
}

// ---------------------------------------------------------------------------
// K3: assign voxel ids (first-occurrence rank), write coors staging, and
// re-tag the map cell with -(vid+1) for kept voxels.
// ---------------------------------------------------------------------------
__global__ void k3_assign(int n) {
    int i = blockIdx.x * BLK + threadIdx.x;
    int warp = threadIdx.x >> 5, lane = threadIdx.x & 31;
    int bit = 0;
    if (i < n) bit = (g_repBits[i >> 5] >> (i & 31)) & 1;
    unsigned m = __ballot_sync(0xffffffffu, bit);
    int lanePre = __popc(m & ((1u << lane) - 1u));
    __shared__ int ws[BLK / 32];
    if (lane == 0) ws[warp] = __popc(m);
    __syncthreads();
    if (threadIdx.x == 0) {
        int acc = 0;
        #pragma unroll
        for (int w = 0; w < BLK / 32; w++) {
            int t = ws[w];
            ws[w] = acc;
            acc += t;
        }
    }
    __syncthreads();
    if (bit) {
        int vid = g_blockOff[blockIdx.x] + ws[warp] + lanePre;
        if (vid < MAXV) {
            int f = g_flat[i];
            g_map[f] = -(vid + 1);
            int z = f % GZ;
            int y = (f / GZ) % GY;
            int x = f / (GZ * GY);
            g_coors[vid * 3 + 0] = z;
            g_coors[vid * 3 + 1] = y;
            g_coors[vid * 3 + 2] = x;
        }
    }
}

// ---------------------------------------------------------------------------
// K4: for each point, if its voxel is kept, count it and ripple-insert its key
// into the 32 slots via atomicMax. Final state: 32 smallest point indices,
// sorted ascending (keys descending), independent of thread interleaving.
// ---------------------------------------------------------------------------
__global__ void k4_insert(int n) {
    int i = blockIdx.x * BLK + threadIdx.x;
    if (i >= n) return;
    int f = g_flat[i];
    if (f < 0) return;
    int v = g_map[f];
    if (v >= 0) return;  // voxel not kept (or empty)
    int vid = -v - 1;
    atomicAdd(&g_cnt[vid], 1);
    unsigned key = (unsigned)(n - i);
    unsigned* base = &g_slots[vid * MAXP];
    #pragma unroll 4
    for (int s = 0; s < MAXP; s++) {
        unsigned old = atomicMax(&base[s], key);
        if (old < key) {
            if (old == 0u) break;  // landed in empty slot, done
            key = old;             // displaced occupant ripples right
        }
        // old >= key: slot keeps old, our key tries next slot
    }
}

// ---------------------------------------------------------------------------
// K5: emit all outputs; reset slots/cnt back to zero.
// Output layout: voxels[60000*32*4] | coors[60000*3] | npv[60000] | voxel_num[1]
// ---------------------------------------------------------------------------
__global__ void k5_emit(const float4* __restrict__ pts, float* __restrict__ out, int n) {
    int idx = blockIdx.x * BLK + threadIdx.x;
    if (idx >= MAXV * MAXP) return;
    int vid = idx >> 5, s = idx & 31;
    unsigned k = g_slots[idx];
    float4 val = make_float4(0.f, 0.f, 0.f, 0.f);
    if (k) {
        g_slots[idx] = 0;
        val = pts[n - (int)k];
    }
    reinterpret_cast<float4*>(out)[idx] = val;
    if (s == 0) {
        int c = g_cnt[vid];
        if (c) g_cnt[vid] = 0;
        if (c > MAXP) c = MAXP;
        const int OC = MAXV * MAXP * 4;      // coors offset
        const int ON = OC + MAXV * 3;        // npv offset
        out[ON + vid] = (float)c;
        int vn = g_voxelNum;
        float cz = 0.f, cy = 0.f, cx = 0.f;
        if (vid < vn) {
            cz = (float)g_coors[vid * 3 + 0];
            cy = (float)g_coors[vid * 3 + 1];
            cx = (float)g_coors[vid * 3 + 2];
        }
        out[OC + vid * 3 + 0] = cz;
        out[OC + vid * 3 + 1] = cy;
        out[OC + vid * 3 + 2] = cx;
        if (idx == 0) out[ON + MAXV] = (float)vn;
    }
}

// ---------------------------------------------------------------------------
// K6: scattered map cleanup (only touched cells) back to zero.
// ---------------------------------------------------------------------------
__global__ void k6_clean(int n) {
    int i = blockIdx.x * BLK + threadIdx.x;
    if (i >= n) return;
    int f = g_flat[i];
    if (f >= 0) g_map[f] = 0;
}

extern "C" void kernel_launch(void* const* d_in, const int* in_sizes, int n_in,
                              void* d_out, int out_size) {
    const float4* pts = (const float4*)d_in[0];
    int n = in_sizes[0] / 4;
    float* out = (float*)d_out;
    int nb = (n + BLK - 1) / BLK;

    k1_claim<<<nb, BLK>>>(pts, n);
    k2_flags<<<nb, BLK>>>(n);
    k_scan<<<1, 1024>>>(nb);
    k3_assign<<<nb, BLK>>>(n);
    k4_insert<<<nb, BLK>>>(n);
    k5_emit<<<(MAXV * MAXP + BLK - 1) / BLK, BLK>>>(pts, out, n);
    k6_clean<<<nb, BLK>>>(n);
}